// round 2
// baseline (speedup 1.0000x reference)
#include <cuda_runtime.h>
#include <math.h>

#define Hd 1024
#define Dm 512
#define Vn 50257
#define Sn 128
#define An 1024
#define Tn 25
#define SOS 1
#define NBLK 148
#define NTHR 1024
#define NWRP 32
#define TOTW (NBLK * NWRP)   /* 4736 warps grid-wide */

// ---------------- persistent device scratch ----------------
__device__ float g_hbuf[2][Hd];
__device__ float g_q[An];
__device__ float g_attn[An];
__device__ float g_scores[Sn];
__device__ int   g_word;
__device__ float g_logZ;
__device__ unsigned long long g_bpk[NBLK];
__device__ float g_bm[NBLK];
__device__ float g_bs[NBLK];
__device__ unsigned g_cnt = 0;
__device__ volatile unsigned g_gen = 0;

__device__ __forceinline__ float warp_sum(float v) {
#pragma unroll
    for (int o = 16; o > 0; o >>= 1) v += __shfl_down_sync(0xffffffffu, v, o);
    return v;
}

// software grid barrier: all 148 blocks are co-resident (grid <= SM count)
__device__ __forceinline__ void gsync() {
    __syncthreads();
    if (threadIdx.x == 0) {
        __threadfence();
        unsigned gen = g_gen;
        if (atomicAdd(&g_cnt, 1u) == NBLK - 1) {
            g_cnt = 0;
            __threadfence();
            g_gen = gen + 1;
        } else {
            while (g_gen == gen) { __nanosleep(64); }
        }
        __threadfence();
    }
    __syncthreads();
}

__global__ void __launch_bounds__(NTHR, 1)
step_kernel(const float* __restrict__ hidden, const float* __restrict__ emb,
            const float* __restrict__ E, const float* __restrict__ Wih,
            const float* __restrict__ Whh, const float* __restrict__ bih,
            const float* __restrict__ bhh, const float* __restrict__ Wq,
            const float* __restrict__ Wout, const float* __restrict__ bout,
            float* __restrict__ out, int step)
{
    const int tid = threadIdx.x, bid = blockIdx.x;
    const int wid = tid >> 5, lane = tid & 31;
    const int hr = step & 1;           // buffer holding h_{t-1}
    const float* h = (step == 0) ? hidden : g_hbuf[hr];
    float* hn = g_hbuf[hr ^ 1];        // h_t

    // ================= Phase A: GRU cell (warp per unit, spread over SMs) =====
    {
        int gw = wid * NBLK + bid;     // unit index, spread across SMs
        if (gw < Hd) {
            int word = (step == 0) ? SOS : g_word;
            const float4* x4 = (const float4*)(E + (size_t)word * Dm);
            const float4* h4 = (const float4*)h;
            const float4* wr_i = (const float4*)(Wih + (size_t)gw * Dm);
            const float4* wz_i = (const float4*)(Wih + (size_t)(Hd + gw) * Dm);
            const float4* wn_i = (const float4*)(Wih + (size_t)(2 * Hd + gw) * Dm);
            const float4* wr_h = (const float4*)(Whh + (size_t)gw * Hd);
            const float4* wz_h = (const float4*)(Whh + (size_t)(Hd + gw) * Hd);
            const float4* wn_h = (const float4*)(Whh + (size_t)(2 * Hd + gw) * Hd);

            float sir = 0.f, siz = 0.f, sin_ = 0.f, shr = 0.f, shz = 0.f, shn = 0.f;
#pragma unroll
            for (int j = 0; j < Dm / 128; j++) {
                float4 xv = x4[lane + 32 * j];
                float4 a = wr_i[lane + 32 * j]; sir  += a.x*xv.x + a.y*xv.y + a.z*xv.z + a.w*xv.w;
                float4 b = wz_i[lane + 32 * j]; siz  += b.x*xv.x + b.y*xv.y + b.z*xv.z + b.w*xv.w;
                float4 c = wn_i[lane + 32 * j]; sin_ += c.x*xv.x + c.y*xv.y + c.z*xv.z + c.w*xv.w;
            }
#pragma unroll
            for (int j = 0; j < Hd / 128; j++) {
                float4 hv = h4[lane + 32 * j];
                float4 a = wr_h[lane + 32 * j]; shr += a.x*hv.x + a.y*hv.y + a.z*hv.z + a.w*hv.w;
                float4 b = wz_h[lane + 32 * j]; shz += b.x*hv.x + b.y*hv.y + b.z*hv.z + b.w*hv.w;
                float4 c = wn_h[lane + 32 * j]; shn += c.x*hv.x + c.y*hv.y + c.z*hv.z + c.w*hv.w;
            }
            sir = warp_sum(sir); siz = warp_sum(siz); sin_ = warp_sum(sin_);
            shr = warp_sum(shr); shz = warp_sum(shz); shn = warp_sum(shn);
            if (lane == 0) {
                float r = 1.f / (1.f + __expf(-(sir + bih[gw]      + shr + bhh[gw])));
                float z = 1.f / (1.f + __expf(-(siz + bih[Hd + gw] + shz + bhh[Hd + gw])));
                float n = tanhf(sin_ + bih[2 * Hd + gw] + r * (shn + bhh[2 * Hd + gw]));
                hn[gw] = (1.f - z) * n + z * h[gw];
            }
        }
    }
    gsync();

    // ================= Phase B: q = Wq @ h_new =================
    {
        int gw = wid * NBLK + bid;
        if (gw < An) {
            const float4* w4 = (const float4*)(Wq + (size_t)gw * Hd);
            const float4* h4 = (const float4*)hn;
            float s = 0.f;
#pragma unroll
            for (int j = 0; j < 8; j++) {
                float4 a = w4[lane + 32 * j], b = h4[lane + 32 * j];
                s += a.x*b.x + a.y*b.y + a.z*b.z + a.w*b.w;
            }
            s = warp_sum(s);
            if (lane == 0) g_q[gw] = s;
        }
    }
    gsync();

    // ================= Phase C: attention scores =================
    {
        int gw = wid * NBLK + bid;
        if (gw < Sn) {
            const float4* e4 = (const float4*)(emb + (size_t)gw * An);
            const float4* q4 = (const float4*)g_q;
            float s = 0.f;
#pragma unroll
            for (int j = 0; j < 8; j++) {
                float4 a = e4[lane + 32 * j], b = q4[lane + 32 * j];
                s += a.x*b.x + a.y*b.y + a.z*b.z + a.w*b.w;
            }
            s = warp_sum(s);
            if (lane == 0) g_scores[gw] = s;
        }
    }
    gsync();

    // ====== Phase D: softmax (redundant per warp) + attn vector (warp per dim) ==
    {
        int d = wid * NBLK + bid;
        if (d < An) {
            float sc0 = g_scores[lane];
            float sc1 = g_scores[lane + 32];
            float sc2 = g_scores[lane + 64];
            float sc3 = g_scores[lane + 96];
            float mx = fmaxf(fmaxf(sc0, sc1), fmaxf(sc2, sc3));
#pragma unroll
            for (int o = 16; o > 0; o >>= 1)
                mx = fmaxf(mx, __shfl_xor_sync(0xffffffffu, mx, o));
            float e0 = __expf(sc0 - mx), e1 = __expf(sc1 - mx);
            float e2 = __expf(sc2 - mx), e3 = __expf(sc3 - mx);
            float ssum = e0 + e1 + e2 + e3;
#pragma unroll
            for (int o = 16; o > 0; o >>= 1)
                ssum += __shfl_xor_sync(0xffffffffu, ssum, o);
            float inv = 1.f / ssum;
            float part = e0 * inv * emb[(size_t)lane * An + d]
                       + e1 * inv * emb[(size_t)(lane + 32) * An + d]
                       + e2 * inv * emb[(size_t)(lane + 64) * An + d]
                       + e3 * inv * emb[(size_t)(lane + 96) * An + d];
            part = warp_sum(part);
            if (lane == 0) g_attn[d] = part;
            if (d == 0) {  // this warp also emits the weights output row
                float* wo = out + (size_t)Tn * Vn + (size_t)step * Sn;
                wo[lane]      = e0 * inv;
                wo[lane + 32] = e1 * inv;
                wo[lane + 64] = e2 * inv;
                wo[lane + 96] = e3 * inv;
            }
        }
    }
    gsync();

    // ================= Phase E: logits GEMV + online logsumexp/argmax =========
    __shared__ __align__(16) float merge[2 * Hd];
    __shared__ unsigned long long spk[NWRP];
    __shared__ float smm[NWRP], ssm[NWRP];
    merge[tid] = hn[tid];
    merge[Hd + tid] = g_attn[tid];
    __syncthreads();

    {
        float wm = __int_as_float(0xff800000);   // -inf
        float ws = 0.f;
        unsigned widx = 0u;
        const int W = bid * NWRP + wid;
        const float4* m4 = (const float4*)merge;
        float* lp = out + (size_t)step * Vn;

        for (int r = W; r < Vn; r += 2 * TOTW) {
            int r2 = r + TOTW;
            bool h2 = (r2 < Vn);
            const float4* w0 = (const float4*)(Wout + (size_t)r * (2 * Hd));
            const float4* w1 = (const float4*)(Wout + (size_t)r2 * (2 * Hd));
            float s0 = 0.f, s1 = 0.f;
#pragma unroll
            for (int j = 0; j < 16; j++) {
                float4 mv = m4[lane + 32 * j];
                float4 a = w0[lane + 32 * j];
                s0 += a.x*mv.x + a.y*mv.y + a.z*mv.z + a.w*mv.w;
                if (h2) {
                    float4 b = w1[lane + 32 * j];
                    s1 += b.x*mv.x + b.y*mv.y + b.z*mv.z + b.w*mv.w;
                }
            }
            s0 = warp_sum(s0);
            s1 = warp_sum(s1);
            if (lane == 0) {
                float l0 = s0 + bout[r];
                lp[r] = l0;
                if (l0 > wm) { ws = ws * __expf(wm - l0) + 1.f; wm = l0; widx = (unsigned)r; }
                else         { ws += __expf(l0 - wm); }
                if (h2) {
                    float l1 = s1 + bout[r2];
                    lp[r2] = l1;
                    if (l1 > wm) { ws = ws * __expf(wm - l1) + 1.f; wm = l1; widx = (unsigned)r2; }
                    else         { ws += __expf(l1 - wm); }
                }
            }
        }
        if (lane == 0) {
            unsigned b = __float_as_uint(wm);
            unsigned key = (b & 0x80000000u) ? ~b : (b | 0x80000000u);
            spk[wid] = ((unsigned long long)key << 32) | (unsigned long long)(0xFFFFFFFFu - widx);
            smm[wid] = wm;
            ssm[wid] = ws;
        }
    }
    __syncthreads();
    if (tid == 0) {
        unsigned long long best = spk[0];
        float Mb = smm[0];
#pragma unroll
        for (int i = 1; i < NWRP; i++) {
            if (spk[i] > best) best = spk[i];
            Mb = fmaxf(Mb, smm[i]);
        }
        float sb = 0.f;
#pragma unroll
        for (int i = 0; i < NWRP; i++) sb += ssm[i] * __expf(smm[i] - Mb);
        g_bpk[bid] = best; g_bm[bid] = Mb; g_bs[bid] = sb;
    }
    gsync();

    // ================= Phase F: global combine (block 0) =================
    {
        __shared__ unsigned long long fpk[NBLK];
        __shared__ float fm[NBLK], fs[NBLK];
        if (bid == 0) {
            if (tid < NBLK) { fpk[tid] = g_bpk[tid]; fm[tid] = g_bm[tid]; fs[tid] = g_bs[tid]; }
            __syncthreads();
            if (tid == 0) {
                unsigned long long best = fpk[0];
                float M = fm[0];
                for (int i = 1; i < NBLK; i++) {
                    if (fpk[i] > best) best = fpk[i];
                    M = fmaxf(M, fm[i]);
                }
                float tot = 0.f;
                for (int i = 0; i < NBLK; i++) tot += fs[i] * __expf(fm[i] - M);
                g_logZ = M + logf(tot);
                int idx = (int)(0xFFFFFFFFu - (unsigned)(best & 0xFFFFFFFFull));
                g_word = idx;
                out[(size_t)Tn * Vn + (size_t)Tn * Sn + step] = (float)idx;
            }
        }
    }
    gsync();

    // ================= Phase G: log_softmax finalize =================
    {
        float lz = g_logZ;
        int v = bid * NTHR + tid;
        if (v < Vn) out[(size_t)step * Vn + v] -= lz;
    }
}

// ---------------- launcher: 25 graph nodes total ----------------
extern "C" void kernel_launch(void* const* d_in, const int* in_sizes, int n_in,
                              void* d_out, int out_size)
{
    const float* hidden = (const float*)d_in[0];
    const float* emb    = (const float*)d_in[1];
    const float* E      = (const float*)d_in[2];
    const float* Wih    = (const float*)d_in[3];
    const float* Whh    = (const float*)d_in[4];
    const float* bih    = (const float*)d_in[5];
    const float* bhh    = (const float*)d_in[6];
    const float* Wq     = (const float*)d_in[7];
    const float* Wout   = (const float*)d_in[8];
    const float* bout   = (const float*)d_in[9];
    float* out = (float*)d_out;

    for (int t = 0; t < Tn; t++) {
        step_kernel<<<NBLK, NTHR>>>(hidden, emb, E, Wih, Whh, bih, bhh,
                                    Wq, Wout, bout, out, t);
    }
}

// round 3
// speedup vs baseline: 1.6889x; 1.6889x over previous
#include <cuda_runtime.h>
#include <cuda_fp16.h>
#include <math.h>

#define Hd 1024
#define Dm 512
#define Vn 50257
#define Sn 128
#define An 1024
#define Tn 25
#define SOS 1
#define NB3 ((Vn + 7) / 8)      /* 6283 logits blocks */
#define NBS 128                 /* small-kernel blocks (<=148, co-resident) */
#define NTS 256                 /* small-kernel threads */

// ---------------- persistent device scratch ----------------
__device__ float g_hbuf[2][Hd];
__device__ float g_q[An];
__device__ float g_attn[An];
__device__ float g_scores[Sn];
__device__ unsigned long long g_bpk[NB3];
__device__ float g_bm[NB3];
__device__ float g_bs[NB3];
__device__ __half g_Wh[(size_t)Vn * 2048];     // fp16 copy of Wout (206 MB)
__device__ unsigned g_cnt = 0;
__device__ volatile unsigned g_gen = 0;

__device__ __forceinline__ float warp_sum(float v) {
#pragma unroll
    for (int o = 16; o > 0; o >>= 1) v += __shfl_down_sync(0xffffffffu, v, o);
    return v;
}
__device__ __forceinline__ unsigned long long umaxll(unsigned long long a, unsigned long long b) {
    return a > b ? a : b;
}

// grid barrier: NBS blocks all co-resident
__device__ __forceinline__ void gsync() {
    __syncthreads();
    if (threadIdx.x == 0) {
        __threadfence();
        unsigned gen = g_gen;
        if (atomicAdd(&g_cnt, 1u) == NBS - 1) {
            g_cnt = 0;
            __threadfence();
            g_gen = gen + 1;
        } else {
            while (g_gen == gen) { __nanosleep(64); }
        }
        __threadfence();
    }
    __syncthreads();
}

// ---------------- K0: Wout fp32 -> fp16 (once per launch) ----------------
__global__ void k_convert(const float* __restrict__ Wout)
{
    const size_t n = (size_t)Vn * 2048 / 8;   // groups of 8 floats
    size_t stride = (size_t)gridDim.x * blockDim.x;
    for (size_t i = (size_t)blockIdx.x * blockDim.x + threadIdx.x; i < n; i += stride) {
        const float4* src = (const float4*)Wout + 2 * i;
        float4 a = src[0], b = src[1];
        uint4 u;
        ((__half2*)&u)[0] = __floats2half2_rn(a.x, a.y);
        ((__half2*)&u)[1] = __floats2half2_rn(a.z, a.w);
        ((__half2*)&u)[2] = __floats2half2_rn(b.x, b.y);
        ((__half2*)&u)[3] = __floats2half2_rn(b.z, b.w);
        ((uint4*)g_Wh)[i] = u;
    }
}

// ------- K1: fused small kernel: [reduce(t-1)+sub] + GRU + q + scores + attn ----
__global__ void __launch_bounds__(NTS, 1)
k_small(const float* __restrict__ hidden, const float* __restrict__ emb,
        const float* __restrict__ E, const float* __restrict__ Wih,
        const float* __restrict__ Whh, const float* __restrict__ bih,
        const float* __restrict__ bhh, const float* __restrict__ Wq,
        float* __restrict__ out, int step)
{
    const int tid = threadIdx.x, bid = blockIdx.x;
    const int wid = tid >> 5, lane = tid & 31;
    int word = SOS;

    // ===== Phase R: finalize step-1 (redundant per block -> no sync before GRU) ==
    if (step > 0) {
        __shared__ unsigned long long rpk[NTS];
        __shared__ float rmx[NTS], rsm[NTS];
        unsigned long long bp = 0ull;
        float M = __int_as_float(0xff800000);
        for (int i = tid; i < NB3; i += NTS) {
            bp = umaxll(bp, g_bpk[i]);
            M = fmaxf(M, g_bm[i]);
        }
        rpk[tid] = bp; rmx[tid] = M;
        __syncthreads();
        for (int s = NTS / 2; s > 0; s >>= 1) {
            if (tid < s) {
                rpk[tid] = umaxll(rpk[tid], rpk[tid + s]);
                rmx[tid] = fmaxf(rmx[tid], rmx[tid + s]);
            }
            __syncthreads();
        }
        M = rmx[0];
        unsigned long long best = rpk[0];
        float sacc = 0.f;
        for (int i = tid; i < NB3; i += NTS) sacc += g_bs[i] * __expf(g_bm[i] - M);
        __syncthreads();
        rsm[tid] = sacc;
        __syncthreads();
        for (int s = NTS / 2; s > 0; s >>= 1) {
            if (tid < s) rsm[tid] += rsm[tid + s];
            __syncthreads();
        }
        float logZ = M + logf(rsm[0]);
        word = (int)(0xFFFFFFFFu - (unsigned)(best & 0xFFFFFFFFull));
        if (bid == 0 && tid == 0)
            out[(size_t)Tn * Vn + (size_t)Tn * Sn + (step - 1)] = (float)word;
        // subtract logZ from lp[step-1] (grid-stride; no barrier needed vs GRU)
        for (int v = bid * NTS + tid; v < Vn; v += NBS * NTS)
            out[(size_t)(step - 1) * Vn + v] -= logZ;
        if (step == Tn) return;    // tail call: finalize only
    }

    const float* h = (step == 0) ? hidden : g_hbuf[(step - 1) & 1];
    float* hn = g_hbuf[step & 1];
    const int gw = bid * 8 + wid;   // 0..1023 (128 blocks x 8 warps)

    // ================= Phase A: GRU (warp per unit) =================
    {
        const float4* x4 = (const float4*)(E + (size_t)word * Dm);
        const float4* h4 = (const float4*)h;
        const float4* wr_i = (const float4*)(Wih + (size_t)gw * Dm);
        const float4* wz_i = (const float4*)(Wih + (size_t)(Hd + gw) * Dm);
        const float4* wn_i = (const float4*)(Wih + (size_t)(2 * Hd + gw) * Dm);
        const float4* wr_h = (const float4*)(Whh + (size_t)gw * Hd);
        const float4* wz_h = (const float4*)(Whh + (size_t)(Hd + gw) * Hd);
        const float4* wn_h = (const float4*)(Whh + (size_t)(2 * Hd + gw) * Hd);

        float sir = 0.f, siz = 0.f, sin_ = 0.f, shr = 0.f, shz = 0.f, shn = 0.f;
#pragma unroll
        for (int j = 0; j < Dm / 128; j++) {
            float4 xv = x4[lane + 32 * j];
            float4 a = wr_i[lane + 32 * j]; sir  += a.x*xv.x + a.y*xv.y + a.z*xv.z + a.w*xv.w;
            float4 b = wz_i[lane + 32 * j]; siz  += b.x*xv.x + b.y*xv.y + b.z*xv.z + b.w*xv.w;
            float4 c = wn_i[lane + 32 * j]; sin_ += c.x*xv.x + c.y*xv.y + c.z*xv.z + c.w*xv.w;
        }
#pragma unroll
        for (int j = 0; j < Hd / 128; j++) {
            float4 hv = h4[lane + 32 * j];
            float4 a = wr_h[lane + 32 * j]; shr += a.x*hv.x + a.y*hv.y + a.z*hv.z + a.w*hv.w;
            float4 b = wz_h[lane + 32 * j]; shz += b.x*hv.x + b.y*hv.y + b.z*hv.z + b.w*hv.w;
            float4 c = wn_h[lane + 32 * j]; shn += c.x*hv.x + c.y*hv.y + c.z*hv.z + c.w*hv.w;
        }
        sir = warp_sum(sir); siz = warp_sum(siz); sin_ = warp_sum(sin_);
        shr = warp_sum(shr); shz = warp_sum(shz); shn = warp_sum(shn);
        if (lane == 0) {
            float r = 1.f / (1.f + __expf(-(sir + bih[gw]      + shr + bhh[gw])));
            float z = 1.f / (1.f + __expf(-(siz + bih[Hd + gw] + shz + bhh[Hd + gw])));
            float n = tanhf(sin_ + bih[2 * Hd + gw] + r * (shn + bhh[2 * Hd + gw]));
            hn[gw] = (1.f - z) * n + z * h[gw];
        }
    }
    gsync();

    // ================= Phase B: q = Wq @ h_new =================
    {
        const float4* w4 = (const float4*)(Wq + (size_t)gw * Hd);
        const float4* h4 = (const float4*)hn;
        float s = 0.f;
#pragma unroll
        for (int j = 0; j < 8; j++) {
            float4 a = w4[lane + 32 * j], b = h4[lane + 32 * j];
            s += a.x*b.x + a.y*b.y + a.z*b.z + a.w*b.w;
        }
        s = warp_sum(s);
        if (lane == 0) g_q[gw] = s;
    }
    gsync();

    // ================= Phase C: attention scores =================
    if (gw < Sn) {
        const float4* e4 = (const float4*)(emb + (size_t)gw * An);
        const float4* q4 = (const float4*)g_q;
        float s = 0.f;
#pragma unroll
        for (int j = 0; j < 8; j++) {
            float4 a = e4[lane + 32 * j], b = q4[lane + 32 * j];
            s += a.x*b.x + a.y*b.y + a.z*b.z + a.w*b.w;
        }
        s = warp_sum(s);
        if (lane == 0) g_scores[gw] = s;
    }
    gsync();

    // ====== Phase D: softmax (redundant per warp) + attn (warp per dim) ======
    {
        float sc0 = g_scores[lane];
        float sc1 = g_scores[lane + 32];
        float sc2 = g_scores[lane + 64];
        float sc3 = g_scores[lane + 96];
        float mx = fmaxf(fmaxf(sc0, sc1), fmaxf(sc2, sc3));
#pragma unroll
        for (int o = 16; o > 0; o >>= 1)
            mx = fmaxf(mx, __shfl_xor_sync(0xffffffffu, mx, o));
        float e0 = __expf(sc0 - mx), e1 = __expf(sc1 - mx);
        float e2 = __expf(sc2 - mx), e3 = __expf(sc3 - mx);
        float ssum = e0 + e1 + e2 + e3;
#pragma unroll
        for (int o = 16; o > 0; o >>= 1)
            ssum += __shfl_xor_sync(0xffffffffu, ssum, o);
        float inv = 1.f / ssum;
        float part = e0 * inv * emb[(size_t)lane * An + gw]
                   + e1 * inv * emb[(size_t)(lane + 32) * An + gw]
                   + e2 * inv * emb[(size_t)(lane + 64) * An + gw]
                   + e3 * inv * emb[(size_t)(lane + 96) * An + gw];
        part = warp_sum(part);
        if (lane == 0) g_attn[gw] = part;
        if (gw == 0) {
            float* wo = out + (size_t)Tn * Vn + (size_t)step * Sn;
            wo[lane]      = e0 * inv;
            wo[lane + 32] = e1 * inv;
            wo[lane + 64] = e2 * inv;
            wo[lane + 96] = e3 * inv;
        }
    }
}

// ---------------- K2: logits GEMV (fp16 weights, warp per row) ----------------
__global__ void k_logits(const float* __restrict__ bout, float* __restrict__ out, int step)
{
    __shared__ __align__(16) float merge[2 * Hd];
    __shared__ unsigned long long spk[8];
    __shared__ float smm[8], ssm[8];
    const int tid = threadIdx.x, wid = tid >> 5, lane = tid & 31;
    const float* hn = g_hbuf[step & 1];
    for (int i = tid; i < Hd; i += 256) { merge[i] = hn[i]; merge[Hd + i] = g_attn[i]; }
    __syncthreads();

    int v = blockIdx.x * 8 + wid;
    float logit = __int_as_float(0xff800000);
    bool valid = (v < Vn);
    if (valid) {
        const uint4* w4 = (const uint4*)(g_Wh + (size_t)v * (2 * Hd));
        const float4* m4 = (const float4*)merge;
        float s = 0.f;
#pragma unroll
        for (int j = 0; j < 8; j++) {
            uint4 u = w4[lane + 32 * j];
            float4 ma = m4[2 * (lane + 32 * j)];
            float4 mb = m4[2 * (lane + 32 * j) + 1];
            const __half2* hp = (const __half2*)&u;
            float2 f0 = __half22float2(hp[0]);
            float2 f1 = __half22float2(hp[1]);
            float2 f2 = __half22float2(hp[2]);
            float2 f3 = __half22float2(hp[3]);
            s += f0.x*ma.x + f0.y*ma.y + f1.x*ma.z + f1.y*ma.w
               + f2.x*mb.x + f2.y*mb.y + f3.x*mb.z + f3.y*mb.w;
        }
        s = warp_sum(s);
        if (lane == 0) {
            logit = s + bout[v];
            out[(size_t)step * Vn + v] = logit;   // raw; logZ subtracted next kernel
        }
    }
    if (lane == 0) {
        unsigned long long pk = 0ull;
        if (valid) {
            unsigned b = __float_as_uint(logit);
            unsigned key = (b & 0x80000000u) ? ~b : (b | 0x80000000u);
            pk = ((unsigned long long)key << 32) |
                 (unsigned long long)(0xFFFFFFFFu - (unsigned)v);
        }
        spk[wid] = pk; smm[wid] = logit;
    }
    __syncthreads();
    if (tid == 0) {
        unsigned long long best = spk[0];
        float M = smm[0];
#pragma unroll
        for (int i = 1; i < 8; i++) {
            best = umaxll(best, spk[i]);
            M = fmaxf(M, smm[i]);
        }
        float tot = 0.f;
#pragma unroll
        for (int i = 0; i < 8; i++) tot += __expf(smm[i] - M);  // -inf -> 0
        g_bpk[blockIdx.x] = best; g_bm[blockIdx.x] = M; g_bs[blockIdx.x] = tot;
    }
}

// ---------------- launcher: 1 + 25*2 + 1 graph nodes ----------------
extern "C" void kernel_launch(void* const* d_in, const int* in_sizes, int n_in,
                              void* d_out, int out_size)
{
    const float* hidden = (const float*)d_in[0];
    const float* emb    = (const float*)d_in[1];
    const float* E      = (const float*)d_in[2];
    const float* Wih    = (const float*)d_in[3];
    const float* Whh    = (const float*)d_in[4];
    const float* bih    = (const float*)d_in[5];
    const float* bhh    = (const float*)d_in[6];
    const float* Wq     = (const float*)d_in[7];
    const float* Wout   = (const float*)d_in[8];
    const float* bout   = (const float*)d_in[9];
    float* out = (float*)d_out;

    k_convert<<<2048, 256>>>(Wout);
    for (int t = 0; t < Tn; t++) {
        k_small <<<NBS, NTS>>>(hidden, emb, E, Wih, Whh, bih, bhh, Wq, out, t);
        k_logits<<<NB3, 256>>>(bout, out, t);
    }
    k_small<<<NBS, NTS>>>(hidden, emb, E, Wih, Whh, bih, bhh, Wq, out, Tn);
}

// round 4
// speedup vs baseline: 1.7725x; 1.0495x over previous
#include <cuda_runtime.h>
#include <cuda_fp16.h>
#include <math.h>

#define Hd 1024
#define Dm 512
#define Vn 50257
#define Sn 128
#define An 1024
#define Tn 25
#define SOS 1
#define NB3 ((Vn + 7) / 8)      /* 6283 logits blocks */
#define NBS 128                 /* small-kernel blocks (co-resident) */
#define NTS 768                 /* small-kernel threads (24 warps) */

// ---------------- persistent device scratch ----------------
__device__ float g_hbuf[2][Hd];
__device__ float g_q[An];
__device__ float g_attn[An];
__device__ float g_scores[Sn];
__device__ float g_logZ;
__device__ unsigned long long g_apk[2];   // packed (key,inv-idx) argmax, per parity
__device__ float g_sum[2];                // sum exp(logit) (ref 0), per parity
__device__ __half g_Wh[(size_t)Vn * 2048];  // fp16 Wout (206 MB)
__device__ unsigned g_cnt = 0;
__device__ volatile unsigned g_gen = 0;

__device__ __forceinline__ float warp_sum(float v) {
#pragma unroll
    for (int o = 16; o > 0; o >>= 1) v += __shfl_down_sync(0xffffffffu, v, o);
    return v;
}
__device__ __forceinline__ unsigned long long umaxll(unsigned long long a, unsigned long long b) {
    return a > b ? a : b;
}

// grid barrier: NBS blocks co-resident
__device__ __forceinline__ void gsync() {
    __syncthreads();
    if (threadIdx.x == 0) {
        __threadfence();
        unsigned gen = g_gen;
        if (atomicAdd(&g_cnt, 1u) == NBS - 1) {
            g_cnt = 0;
            __threadfence();
            g_gen = gen + 1;
        } else {
            while (g_gen == gen) { __nanosleep(64); }
        }
        __threadfence();
    }
    __syncthreads();
}

// ---------------- K0: Wout fp32 -> fp16 (once per launch) ----------------
__global__ void k_convert(const float* __restrict__ Wout)
{
    const size_t n = (size_t)Vn * 2048 / 8;
    size_t stride = (size_t)gridDim.x * blockDim.x;
    for (size_t i = (size_t)blockIdx.x * blockDim.x + threadIdx.x; i < n; i += stride) {
        const float4* src = (const float4*)Wout + 2 * i;
        float4 a = src[0], b = src[1];
        uint4 u;
        ((__half2*)&u)[0] = __floats2half2_rn(a.x, a.y);
        ((__half2*)&u)[1] = __floats2half2_rn(a.z, a.w);
        ((__half2*)&u)[2] = __floats2half2_rn(b.x, b.y);
        ((__half2*)&u)[3] = __floats2half2_rn(b.z, b.w);
        ((uint4*)g_Wh)[i] = u;
    }
}

// ---- K1: fused small kernel: scalar finalize + GRU + q + scores + attn ----
__global__ void __launch_bounds__(NTS, 1)
k_small(const float* __restrict__ hidden, const float* __restrict__ emb,
        const float* __restrict__ E, const float* __restrict__ Wih,
        const float* __restrict__ Whh, const float* __restrict__ bih,
        const float* __restrict__ bhh, const float* __restrict__ Wq,
        float* __restrict__ out, int step)
{
    const int tid = threadIdx.x, bid = blockIdx.x;
    const int wid = tid >> 5, lane = tid & 31;

    __shared__ float sgi[8][3], sgh[8][3];
    __shared__ float sq[8][2];
    __shared__ float scred[16];

    int word = SOS;
    if (step > 0) {
        unsigned long long best = g_apk[(step - 1) & 1];
        word = (int)(0xFFFFFFFFu - (unsigned)(best & 0xFFFFFFFFull));
        float logZ = logf(g_sum[(step - 1) & 1]);
        if (bid == 0 && tid == 0) {
            g_logZ = logZ;
            out[(size_t)Tn * Vn + (size_t)Tn * Sn + (step - 1)] = (float)word;
        }
        if (step == Tn) {   // tail: only finalize last step's log_softmax
            for (int v = bid * NTS + tid; v < Vn; v += NBS * NTS)
                out[(size_t)(step - 1) * Vn + v] -= logZ;
            return;
        }
    }
    // reset accumulation slot this step's k_logits will use
    if (bid == 0 && tid == 0) { g_apk[step & 1] = 0ull; g_sum[step & 1] = 0.f; }

    const float* h = (step == 0) ? hidden : g_hbuf[(step - 1) & 1];
    float* hn = g_hbuf[step & 1];

    // ===== Phase A: GRU — warp per (unit, gate): 8 units x 3 gates = 24 warps ====
    {
        const int ul = wid / 3;        // local unit 0..7
        const int g  = wid % 3;        // gate 0=r 1=z 2=n
        const int u  = bid * 8 + ul;   // global unit
        const int row = g * Hd + u;
        const float4* x4 = (const float4*)(E + (size_t)word * Dm);
        const float4* h4 = (const float4*)h;
        const float4* wi = (const float4*)(Wih + (size_t)row * Dm);
        const float4* wh = (const float4*)(Whh + (size_t)row * Hd);
        float si = 0.f, sh = 0.f;
#pragma unroll
        for (int j = 0; j < Dm / 128; j++) {      // 4
            float4 a = wi[lane + 32 * j], xv = x4[lane + 32 * j];
            si += a.x*xv.x + a.y*xv.y + a.z*xv.z + a.w*xv.w;
        }
#pragma unroll
        for (int j = 0; j < Hd / 128; j++) {      // 8
            float4 a = wh[lane + 32 * j], hv = h4[lane + 32 * j];
            sh += a.x*hv.x + a.y*hv.y + a.z*hv.z + a.w*hv.w;
        }
        si = warp_sum(si); sh = warp_sum(sh);
        if (lane == 0) { sgi[ul][g] = si + bih[row]; sgh[ul][g] = sh + bhh[row]; }
        __syncthreads();
        if (tid < 8) {
            int u2 = bid * 8 + tid;
            float r = 1.f / (1.f + __expf(-(sgi[tid][0] + sgh[tid][0])));
            float z = 1.f / (1.f + __expf(-(sgi[tid][1] + sgh[tid][1])));
            float n = tanhf(sgi[tid][2] + r * sgh[tid][2]);
            hn[u2] = (1.f - z) * n + z * h[u2];
        }
    }
    gsync();

    // ===== Phase B: q = Wq @ h_new — 2 warps per row, 8 rows per block =========
    if (wid < 16) {
        const int ul = wid >> 1, half = wid & 1;
        const int u = bid * 8 + ul;
        const float4* w4 = (const float4*)(Wq + (size_t)u * Hd) + half * 128;
        const float4* h4 = (const float4*)hn + half * 128;
        float s = 0.f;
#pragma unroll
        for (int j = 0; j < 4; j++) {
            float4 a = w4[lane + 32 * j], b = h4[lane + 32 * j];
            s += a.x*b.x + a.y*b.y + a.z*b.z + a.w*b.w;
        }
        s = warp_sum(s);
        if (lane == 0) sq[ul][half] = s;
    }
    __syncthreads();
    if (tid < 8) g_q[bid * 8 + tid] = sq[tid][0] + sq[tid][1];
    gsync();

    // ===== Phase C: scores — block bid computes score[bid] (512 threads) =======
    if (tid < 512) {
        float2 e2 = ((const float2*)(emb + (size_t)bid * An))[tid];
        float2 q2 = ((const float2*)g_q)[tid];
        float s = e2.x * q2.x + e2.y * q2.y;
        s = warp_sum(s);
        if (lane == 0) scred[wid] = s;
    }
    __syncthreads();
    if (tid == 0) {
        float s = 0.f;
#pragma unroll
        for (int i = 0; i < 16; i++) s += scred[i];
        g_scores[bid] = s;
    }
    gsync();

    // ===== Phase D: softmax (per-warp redundant) + attn — warp per dim =========
    if (wid < 8) {
        const int d = bid + NBS * wid;   // 0..1023
        float sc0 = g_scores[lane];
        float sc1 = g_scores[lane + 32];
        float sc2 = g_scores[lane + 64];
        float sc3 = g_scores[lane + 96];
        float mx = fmaxf(fmaxf(sc0, sc1), fmaxf(sc2, sc3));
#pragma unroll
        for (int o = 16; o > 0; o >>= 1)
            mx = fmaxf(mx, __shfl_xor_sync(0xffffffffu, mx, o));
        float e0 = __expf(sc0 - mx), e1 = __expf(sc1 - mx);
        float e2 = __expf(sc2 - mx), e3 = __expf(sc3 - mx);
        float ssum = e0 + e1 + e2 + e3;
#pragma unroll
        for (int o = 16; o > 0; o >>= 1)
            ssum += __shfl_xor_sync(0xffffffffu, ssum, o);
        float inv = 1.f / ssum;
        float part = e0 * inv * emb[(size_t)lane * An + d]
                   + e1 * inv * emb[(size_t)(lane + 32) * An + d]
                   + e2 * inv * emb[(size_t)(lane + 64) * An + d]
                   + e3 * inv * emb[(size_t)(lane + 96) * An + d];
        part = warp_sum(part);
        if (lane == 0) g_attn[d] = part;
        if (d == 0) {
            float* wo = out + (size_t)Tn * Vn + (size_t)step * Sn;
            wo[lane]      = e0 * inv;
            wo[lane + 32] = e1 * inv;
            wo[lane + 64] = e2 * inv;
            wo[lane + 96] = e3 * inv;
        }
    }
}

// ---------------- K2: logits GEMV (fp16) + atomic logsumexp/argmax ----------
__global__ void k_logits(const float* __restrict__ bout, float* __restrict__ out, int step)
{
    __shared__ __align__(16) float merge[2 * Hd];
    __shared__ unsigned long long spk[8];
    __shared__ float sse[8];
    const int tid = threadIdx.x, wid = tid >> 5, lane = tid & 31;
    const float* hn = g_hbuf[step & 1];

    // finalize previous step's row for our 8 vocab entries (coalesced 32B)
    if (step > 0 && tid < 8) {
        int pv = blockIdx.x * 8 + tid;
        if (pv < Vn) out[(size_t)(step - 1) * Vn + pv] -= g_logZ;
    }
    for (int i = tid; i < Hd; i += 256) { merge[i] = hn[i]; merge[Hd + i] = g_attn[i]; }
    __syncthreads();

    int v = blockIdx.x * 8 + wid;
    float logit = __int_as_float(0xff800000);
    bool valid = (v < Vn);
    if (valid) {
        const uint4* w4 = (const uint4*)(g_Wh + (size_t)v * (2 * Hd));
        const float4* m4 = (const float4*)merge;
        float s = 0.f;
#pragma unroll
        for (int j = 0; j < 8; j++) {
            uint4 u = w4[lane + 32 * j];
            float4 ma = m4[2 * (lane + 32 * j)];
            float4 mb = m4[2 * (lane + 32 * j) + 1];
            const __half2* hp = (const __half2*)&u;
            float2 f0 = __half22float2(hp[0]);
            float2 f1 = __half22float2(hp[1]);
            float2 f2 = __half22float2(hp[2]);
            float2 f3 = __half22float2(hp[3]);
            s += f0.x*ma.x + f0.y*ma.y + f1.x*ma.z + f1.y*ma.w
               + f2.x*mb.x + f2.y*mb.y + f3.x*mb.z + f3.y*mb.w;
        }
        s = warp_sum(s);
        if (lane == 0) {
            logit = s + bout[v];
            out[(size_t)step * Vn + v] = logit;   // raw; subtracted next step
        }
    }
    if (lane == 0) {
        unsigned long long pk = 0ull;
        float e = 0.f;
        if (valid) {
            unsigned b = __float_as_uint(logit);
            unsigned key = (b & 0x80000000u) ? ~b : (b | 0x80000000u);
            pk = ((unsigned long long)key << 32) |
                 (unsigned long long)(0xFFFFFFFFu - (unsigned)v);
            e = __expf(logit);    // reference 0: logits are O(few), safe
        }
        spk[wid] = pk; sse[wid] = e;
    }
    __syncthreads();
    if (tid == 0) {
        unsigned long long best = spk[0];
        float tot = sse[0];
#pragma unroll
        for (int i = 1; i < 8; i++) { best = umaxll(best, spk[i]); tot += sse[i]; }
        atomicMax(&g_apk[step & 1], best);
        atomicAdd(&g_sum[step & 1], tot);
    }
}

// ---------------- launcher ----------------
extern "C" void kernel_launch(void* const* d_in, const int* in_sizes, int n_in,
                              void* d_out, int out_size)
{
    const float* hidden = (const float*)d_in[0];
    const float* emb    = (const float*)d_in[1];
    const float* E      = (const float*)d_in[2];
    const float* Wih    = (const float*)d_in[3];
    const float* Whh    = (const float*)d_in[4];
    const float* bih    = (const float*)d_in[5];
    const float* bhh    = (const float*)d_in[6];
    const float* Wq     = (const float*)d_in[7];
    const float* Wout   = (const float*)d_in[8];
    const float* bout   = (const float*)d_in[9];
    float* out = (float*)d_out;

    k_convert<<<2048, 256>>>(Wout);
    for (int t = 0; t < Tn; t++) {
        k_small <<<NBS, NTS>>>(hidden, emb, E, Wih, Whh, bih, bhh, Wq, out, t);
        k_logits<<<NB3, 256>>>(bout, out, t);
    }
    k_small<<<NBS, NTS>>>(hidden, emb, E, Wih, Whh, bih, bhh, Wq, out, Tn);
}